// round 16
// baseline (speedup 1.0000x reference)
#include <cuda_runtime.h>
#include <cuda_fp16.h>
#include <cstdint>

// ---------------------------------------------------------------------------
// MultiAttnLayer, sm_103 baseline-ISA path. Round 16: PERSISTENT GEMM —
// grid = 2 CTAs/SM, each CTA loops over output tiles with the cp.async.bulk
// stage ring and cross-iteration fragment prefetch running continuously
// across tile boundaries (prologue/epilogue/tail all hidden). Single fused
// convert kernel. Blocked swizzled tiles end-to-end, fp16 dataflow.
// ---------------------------------------------------------------------------

constexpr int BB   = 4;
constexpr int SEQ  = 8192;
constexpr int DM   = 1024;
constexpr int NH   = 16;
constexpr int HD   = 64;
constexpr int WIN  = 128;
constexpr int NWIN = SEQ / WIN;
constexpr int FF   = 4096;
constexpr int T    = BB * SEQ;
constexpr float LN_EPS = 1e-5f;

// Scratch (device globals). *_b = blocked swizzled 128x64 tiles.
__device__ __half g_src_b[(size_t)T * DM];
__device__ __half g_win_b[3 * DM * DM];
__device__ __half g_wout_b[DM * DM];
__device__ __half g_w1_b[FF * DM];
__device__ __half g_w2_b[DM * FF];
__device__ __half g_qkv_b[(size_t)T * 3 * DM];
__device__ __half g_ctx_b[(size_t)T * DM];
__device__ __half g_h16_b[(size_t)T * DM];
__device__ __half g_ff_b[(size_t)T * FF];
__device__ __half g_x16[(size_t)T * DM];

// ========================= helpers =========================================
__device__ __forceinline__ uint32_t smem_u32(const void* p) {
    uint32_t a;
    asm("{ .reg .u64 t; cvta.to.shared.u64 t, %1; cvt.u32.u64 %0, t; }" : "=r"(a) : "l"(p));
    return a;
}
__device__ __forceinline__ void bulk_g2s(uint32_t dst, const void* src,
                                         uint32_t bytes, uint32_t mbar) {
    asm volatile(
        "cp.async.bulk.shared::cluster.global.mbarrier::complete_tx::bytes "
        "[%0], [%1], %2, [%3];"
        :: "r"(dst), "l"(src), "r"(bytes), "r"(mbar) : "memory");
}
#define MBARRIER_INIT(addr, cnt) \
    asm volatile("mbarrier.init.shared.b64 [%0], %1;" :: "r"((uint32_t)(addr)), "r"((uint32_t)(cnt)) : "memory")
#define MBARRIER_EXPECT_TX(addr, tx) \
    asm volatile("mbarrier.arrive.expect_tx.shared.b64 _, [%0], %1;" \
        :: "r"((uint32_t)(addr)), "r"((uint32_t)(tx)) : "memory")
#define MBARRIER_WAIT_PARITY(addr, ph) do {                                      \
    uint32_t _m = (uint32_t)(addr), _p = (uint32_t)(ph), _d;                     \
    asm volatile("{ .reg .pred p; mbarrier.try_wait.parity.acquire.cta.shared::cta.b64 p, [%1], %2; selp.b32 %0, 1, 0, p; }" \
        : "=r"(_d) : "r"(_m), "r"(_p) : "memory");                               \
    if (!_d) {                                                                   \
        asm volatile("{ .reg .pred P1; WL_%=: mbarrier.try_wait.parity.acquire.cta.shared::cta.b64 P1, [%0], %1, 0x989680; @P1 bra.uni WD_%=; bra.uni WL_%=; WD_%=: }" \
            :: "r"(_m), "r"(_p) : "memory");                                     \
    }                                                                            \
} while (0)
#define LDSM_X4(r0, r1, r2, r3, addr)                                          \
    asm volatile("ldmatrix.sync.aligned.m8n8.x4.shared.b16 {%0,%1,%2,%3}, [%4];" \
        : "=r"(r0), "=r"(r1), "=r"(r2), "=r"(r3) : "r"(addr))
#define LDSM_X4_T(r0, r1, r2, r3, addr)                                        \
    asm volatile("ldmatrix.sync.aligned.m8n8.x4.trans.shared.b16 {%0,%1,%2,%3}, [%4];" \
        : "=r"(r0), "=r"(r1), "=r"(r2), "=r"(r3) : "r"(addr))

__device__ __forceinline__ void mma_f16(float c[4], const uint32_t a[4],
                                        uint32_t b0, uint32_t b1) {
    asm volatile(
        "mma.sync.aligned.m16n8k16.row.col.f32.f16.f16.f32 "
        "{%0,%1,%2,%3}, {%4,%5,%6,%7}, {%8,%9}, {%0,%1,%2,%3};\n"
        : "+f"(c[0]), "+f"(c[1]), "+f"(c[2]), "+f"(c[3])
        : "r"(a[0]), "r"(a[1]), "r"(a[2]), "r"(a[3]), "r"(b0), "r"(b1));
}

__device__ __forceinline__ size_t blk_off(int row, int col, int C) {
    int tile = (row >> 7) * (C >> 6) + (col >> 6);
    int r = row & 127;
    int g = (col & 63) >> 3;
    return ((size_t)tile << 13) + (size_t)r * 64 + (size_t)((g ^ (r & 7)) << 3) + (col & 7);
}

// ========================= persistent fp16 GEMM ============================
constexpr int BM = 128, BN = 128, BK = 64, STAGES = 3;
constexpr int TILE_B  = 16384;
constexpr int ST      = 2 * TILE_B;
constexpr int MBAR_OFF = STAGES * ST;
constexpr int GEMM_SMEM = MBAR_OFF + 32;

template <int OUT_BLK, int RELU, int RES, int KV>
__global__ __launch_bounds__(128, 2)
void gemm_h(const __half* __restrict__ Ablk, const __half* __restrict__ Wblk,
            const float* __restrict__ bias, const __half* __restrict__ Res,
            __half* __restrict__ Cout, int M, int N)
{
    extern __shared__ char smraw[];
    const uint32_t sb = smem_u32(smraw);
    const uint32_t mb = sb + MBAR_OFF;

    const int tid  = threadIdx.x;
    const int wid  = tid >> 5;
    const int lane = tid & 31;
    const int wm   = wid >> 1;
    const int wn   = wid & 1;
    constexpr int K  = KV;
    constexpr int KT = K / 64;
    constexpr int NK = K / BK;     // power of 2 (16 or 64)

    const int GRID = gridDim.x;
    const int cta  = blockIdx.x;
    const int NTN  = N >> 7;
    const int NTOT = (M >> 7) * NTN;
    const int ntl  = (NTOT - cta + GRID - 1) / GRID;   // tiles for this CTA
    if (ntl <= 0) return;
    const int L = ntl * NK;                            // local iterations

    // tile pointers for local iteration j
    auto aptr = [&](int j) -> const __half* {
        int t = cta + (j / NK) * GRID;
        return Ablk + (((size_t)(t / NTN) * KT + (j & (NK - 1))) << 13);
    };
    auto wptr = [&](int j) -> const __half* {
        int t = cta + (j / NK) * GRID;
        return Wblk + (((size_t)(t % NTN) * KT + (j & (NK - 1))) << 13);
    };

    float acc[4][8][4];
#pragma unroll
    for (int i = 0; i < 4; i++)
#pragma unroll
        for (int j = 0; j < 8; j++)
#pragma unroll
            for (int l = 0; l < 4; l++) acc[i][j][l] = 0.f;

    if (tid == 0) {
#pragma unroll
        for (int s = 0; s < STAGES; s++) MBARRIER_INIT(mb + s * 8, 1);
    }
    __syncthreads();

    if (tid == 0) {
#pragma unroll
        for (int s = 0; s < STAGES - 1; s++) {   // L >= NK >= 16 > 2
            MBARRIER_EXPECT_TX(mb + s * 8, (uint32_t)ST);
            bulk_g2s(sb + s * ST,          aptr(s), TILE_B, mb + s * 8);
            bulk_g2s(sb + s * ST + TILE_B, wptr(s), TILE_B, mb + s * 8);
        }
    }

    const int r7A = lane & 7;
    const int hbA = lane >> 4;
    const uint32_t a_rowbyte = (uint32_t)((wm * 64 + (lane & 15)) * 128);
    const int r7B = lane & 7;
    const int hbB = (lane >> 3) & 1;
    const uint32_t b_rowbyte = (uint32_t)((wn * 64 + (lane & 7) + ((lane >> 4) & 1) * 8) * 128);

    uint32_t a_f[2][4][4];
    uint32_t b_f[2][8][2];

    // Initial prime: wait stage 0, load (li=0, ks=0) fragments into buffer 0.
    MBARRIER_WAIT_PARITY(mb, 0);
    {
        const uint32_t a_row = sb + a_rowbyte;
        const uint32_t b_row = sb + TILE_B + b_rowbyte;
        const uint32_t ax = (uint32_t)((hbA ^ r7A) << 4);
#pragma unroll
        for (int im = 0; im < 4; im++)
            LDSM_X4(a_f[0][im][0], a_f[0][im][1], a_f[0][im][2], a_f[0][im][3],
                    a_row + im * 2048 + ax);
        const uint32_t bx = (uint32_t)((hbB ^ r7B) << 4);
#pragma unroll
        for (int p = 0; p < 4; p++) {
            uint32_t r0, r1, r2, r3;
            LDSM_X4(r0, r1, r2, r3, b_row + p * 2048 + bx);
            b_f[0][2 * p][0] = r0; b_f[0][2 * p][1] = r1;
            b_f[0][2 * p + 1][0] = r2; b_f[0][2 * p + 1][1] = r3;
        }
    }

    int bm = ((cta / NTN) << 7);     // tile 0 coords for this CTA
    int bn = ((cta % NTN) << 7);

    for (int li = 0; li < L; li++) {
        __syncthreads();   // readers of slot (li+2)%S finished at iter li-1
        if (li + 2 < L && tid == 0) {
            const int lj = li + 2;
            const int sN = lj % STAGES;
            MBARRIER_EXPECT_TX(mb + sN * 8, (uint32_t)ST);
            bulk_g2s(sb + sN * ST,          aptr(lj), TILE_B, mb + sN * 8);
            bulk_g2s(sb + sN * ST + TILE_B, wptr(lj), TILE_B, mb + sN * 8);
        }

        const uint32_t aSt = sb + (li % STAGES) * ST;
        const uint32_t a_row = aSt + a_rowbyte;
        const uint32_t b_row = aSt + TILE_B + b_rowbyte;

#pragma unroll
        for (int ks = 0; ks < 4; ks++) {
            const int cb = ks & 1;
            const int nb = cb ^ 1;
            if (ks < 3) {
                const uint32_t ax = (uint32_t)(((2 * (ks + 1) + hbA) ^ r7A) << 4);
#pragma unroll
                for (int im = 0; im < 4; im++)
                    LDSM_X4(a_f[nb][im][0], a_f[nb][im][1], a_f[nb][im][2], a_f[nb][im][3],
                            a_row + im * 2048 + ax);
                const uint32_t bx = (uint32_t)(((2 * (ks + 1) + hbB) ^ r7B) << 4);
#pragma unroll
                for (int p = 0; p < 4; p++) {
                    uint32_t r0, r1, r2, r3;
                    LDSM_X4(r0, r1, r2, r3, b_row + p * 2048 + bx);
                    b_f[nb][2 * p][0] = r0; b_f[nb][2 * p][1] = r1;
                    b_f[nb][2 * p + 1][0] = r2; b_f[nb][2 * p + 1][1] = r3;
                }
            } else if (li + 1 < L) {
                // cross-iteration (possibly cross-tile) prefetch of (li+1, ks=0)
                MBARRIER_WAIT_PARITY(mb + ((li + 1) % STAGES) * 8, ((li + 1) / STAGES) & 1);
                const uint32_t aS2 = sb + ((li + 1) % STAGES) * ST;
                const uint32_t aR2 = aS2 + a_rowbyte;
                const uint32_t bR2 = aS2 + TILE_B + b_rowbyte;
                const uint32_t ax = (uint32_t)((hbA ^ r7A) << 4);
#pragma unroll
                for (int im = 0; im < 4; im++)
                    LDSM_X4(a_f[nb][im][0], a_f[nb][im][1], a_f[nb][im][2], a_f[nb][im][3],
                            aR2 + im * 2048 + ax);
                const uint32_t bx = (uint32_t)((hbB ^ r7B) << 4);
#pragma unroll
                for (int p = 0; p < 4; p++) {
                    uint32_t r0, r1, r2, r3;
                    LDSM_X4(r0, r1, r2, r3, bR2 + p * 2048 + bx);
                    b_f[nb][2 * p][0] = r0; b_f[nb][2 * p][1] = r1;
                    b_f[nb][2 * p + 1][0] = r2; b_f[nb][2 * p + 1][1] = r3;
                }
            }
#pragma unroll
            for (int im = 0; im < 4; im++)
#pragma unroll
                for (int n = 0; n < 8; n++)
                    mma_f16(acc[im][n], a_f[cb][im], b_f[cb][n][0], b_f[cb][n][1]);
        }

        // Epilogue at tile end (pipeline keeps running for next tile).
        if ((li & (NK - 1)) == NK - 1) {
#pragma unroll
            for (int im = 0; im < 4; im++) {
                const int row = bm + wm * 64 + im * 16 + (lane >> 2);
#pragma unroll
                for (int n = 0; n < 8; n++) {
                    const int col = bn + wn * 64 + n * 8 + (lane & 3) * 2;
                    const float2 bv = *(const float2*)(bias + col);
                    float v00 = acc[im][n][0] + bv.x, v01 = acc[im][n][1] + bv.y;
                    float v10 = acc[im][n][2] + bv.x, v11 = acc[im][n][3] + bv.y;
                    if (RES) {
                        const float2 r0 = __half22float2(
                            *(const __half2*)(Res + blk_off(row, col, N)));
                        const float2 r1 = __half22float2(
                            *(const __half2*)(Res + blk_off(row + 8, col, N)));
                        v00 += r0.x; v01 += r0.y;
                        v10 += r1.x; v11 += r1.y;
                    }
                    if (RELU) {
                        v00 = fmaxf(v00, 0.f); v01 = fmaxf(v01, 0.f);
                        v10 = fmaxf(v10, 0.f); v11 = fmaxf(v11, 0.f);
                    }
                    if (OUT_BLK) {
                        *(__half2*)(Cout + blk_off(row, col, N))     = __floats2half2_rn(v00, v01);
                        *(__half2*)(Cout + blk_off(row + 8, col, N)) = __floats2half2_rn(v10, v11);
                    } else {
                        *(__half2*)(Cout + (size_t)row * N + col)       = __floats2half2_rn(v00, v01);
                        *(__half2*)(Cout + (size_t)(row + 8) * N + col) = __floats2half2_rn(v10, v11);
                    }
                    acc[im][n][0] = 0.f; acc[im][n][1] = 0.f;
                    acc[im][n][2] = 0.f; acc[im][n][3] = 0.f;
                }
            }
            // next tile coords
            const int tNext = cta + ((li + 1) / NK) * GRID;
            if (tNext < NTOT) {
                bm = (tNext / NTN) << 7;
                bn = (tNext % NTN) << 7;
            }
        }
    }
}

// ===================== window-local attention (R14/15) ======================
constexpr int ATT_MB   = 0;
constexpr int OFF_Q    = 1024;
constexpr int OFF_K    = OFF_Q + TILE_B;
constexpr int OFF_V    = OFF_K + TILE_B;
constexpr int OFF_P    = OFF_V + TILE_B;
constexpr int P_ROWB   = 272;
constexpr int ATTN_SMEM = OFF_P + 128 * P_ROWB;

__global__ __launch_bounds__(256, 2)
void attn_h()
{
    extern __shared__ char smraw[];
    const uint32_t sb = smem_u32(smraw);
    const uint32_t mb = sb + ATT_MB;
    const uint32_t qh = sb + OFF_Q;
    const uint32_t kh = sb + OFF_K;
    const uint32_t vh = sb + OFF_V;

    const int h  = blockIdx.x;
    const int w  = blockIdx.y;
    const int b  = blockIdx.z;
    const int t0 = b * SEQ + w * WIN;
    const int rt = t0 >> 7;

    const int tid  = threadIdx.x;
    const int wid  = tid >> 5;
    const int lane = tid & 31;
    const int gid  = lane >> 2;
    const int tig  = lane & 3;

    if (tid == 0) MBARRIER_INIT(mb, 1);
    __syncthreads();
    if (tid == 0) {
        MBARRIER_EXPECT_TX(mb, 3u * TILE_B);
        const size_t trow = (size_t)rt * 48;
        bulk_g2s(qh, g_qkv_b + ((trow + h)      << 13), TILE_B, mb);
        bulk_g2s(kh, g_qkv_b + ((trow + 16 + h) << 13), TILE_B, mb);
        bulk_g2s(vh, g_qkv_b + ((trow + 32 + h) << 13), TILE_B, mb);
    }
    MBARRIER_WAIT_PARITY(mb, 0);

    const int m0 = wid * 16;

    float sc[16][4];
#pragma unroll
    for (int n = 0; n < 16; n++)
#pragma unroll
        for (int l = 0; l < 4; l++) sc[n][l] = 0.f;

    const int aRow = m0 + (lane & 15);
    const int aHb  = lane >> 4;
    const uint32_t a_row = qh + (uint32_t)aRow * 128;
    const int aR7 = aRow & 7;
    const int bRowBase = (lane & 7) + ((lane >> 4) & 1) * 8;
    const int bHb = (lane >> 3) & 1;

#pragma unroll
    for (int ks = 0; ks < 4; ks++) {
        uint32_t a[4];
        LDSM_X4(a[0], a[1], a[2], a[3], a_row + (uint32_t)(((2 * ks + aHb) ^ aR7) << 4));
#pragma unroll
        for (int p = 0; p < 8; p++) {
            const int brow = bRowBase + p * 16;
            const uint32_t baddr = kh + (uint32_t)brow * 128 +
                                   (uint32_t)(((2 * ks + bHb) ^ (brow & 7)) << 4);
            uint32_t r0, r1, r2, r3;
            LDSM_X4(r0, r1, r2, r3, baddr);
            mma_f16(sc[2 * p], a, r0, r1);
            mma_f16(sc[2 * p + 1], a, r2, r3);
        }
    }

    const float scale = 0.125f;
    float mA = -1e30f, mB = -1e30f;
#pragma unroll
    for (int n = 0; n < 16; n++) {
#pragma unroll
        for (int l = 0; l < 4; l++) sc[n][l] *= scale;
        mA = fmaxf(mA, fmaxf(sc[n][0], sc[n][1]));
        mB = fmaxf(mB, fmaxf(sc[n][2], sc[n][3]));
    }
    mA = fmaxf(mA, __shfl_xor_sync(0xffffffffu, mA, 1));
    mA = fmaxf(mA, __shfl_xor_sync(0xffffffffu, mA, 2));
    mB = fmaxf(mB, __shfl_xor_sync(0xffffffffu, mB, 1));
    mB = fmaxf(mB, __shfl_xor_sync(0xffffffffu, mB, 2));

    float sA = 0.f, sB = 0.f;
#pragma unroll
    for (int n = 0; n < 16; n++) {
        sc[n][0] = __expf(sc[n][0] - mA);
        sc[n][1] = __expf(sc[n][1] - mA);
        sc[n][2] = __expf(sc[n][2] - mB);
        sc[n][3] = __expf(sc[n][3] - mB);
        sA += sc[n][0] + sc[n][1];
        sB += sc[n][2] + sc[n][3];
    }
    sA += __shfl_xor_sync(0xffffffffu, sA, 1);
    sA += __shfl_xor_sync(0xffffffffu, sA, 2);
    sB += __shfl_xor_sync(0xffffffffu, sB, 1);
    sB += __shfl_xor_sync(0xffffffffu, sB, 2);
    const float invA = 1.f / sA, invB = 1.f / sB;

    {
        const int rA = m0 + gid;
        __half2* pA = (__half2*)(smraw + OFF_P + rA * P_ROWB);
        __half2* pB = (__half2*)(smraw + OFF_P + (rA + 8) * P_ROWB);
#pragma unroll
        for (int n = 0; n < 16; n++) {
            const int c2 = (n * 8 + tig * 2) >> 1;
            pA[c2] = __floats2half2_rn(sc[n][0] * invA, sc[n][1] * invA);
            pB[c2] = __floats2half2_rn(sc[n][2] * invB, sc[n][3] * invB);
        }
    }
    __syncthreads();

    float o[8][4];
#pragma unroll
    for (int n = 0; n < 8; n++)
#pragma unroll
        for (int l = 0; l < 4; l++) o[n][l] = 0.f;

    const uint32_t p_base = sb + OFF_P + (m0 + (lane & 15)) * P_ROWB + (lane >> 4) * 16;
    const int vRowBase = (lane & 7) + ((lane >> 3) & 1) * 8;
    const int vGb = lane >> 4;

#pragma unroll
    for (int ks = 0; ks < 8; ks++) {
        uint32_t a[4];
        LDSM_X4(a[0], a[1], a[2], a[3], p_base + ks * 32);
        const int vrow = vRowBase + ks * 16;
        const uint32_t vr = vh + (uint32_t)vrow * 128;
        const int v7 = vrow & 7;
#pragma unroll
        for (int p = 0; p < 4; p++) {
            uint32_t r0, r1, r2, r3;
            LDSM_X4_T(r0, r1, r2, r3, vr + (uint32_t)(((2 * p + vGb) ^ v7) << 4));
            mma_f16(o[2 * p], a, r0, r1);
            mma_f16(o[2 * p + 1], a, r2, r3);
        }
    }

    {
        const size_t tbase = (((size_t)rt * (DM >> 6)) + h) << 13;
        const int rA = m0 + gid;
        const int rB = rA + 8;
#pragma unroll
        for (int n = 0; n < 8; n++) {
            __half2* oA = (__half2*)(g_ctx_b + tbase + (size_t)rA * 64 +
                                     ((n ^ (rA & 7)) << 3) + tig * 2);
            __half2* oB = (__half2*)(g_ctx_b + tbase + (size_t)rB * 64 +
                                     ((n ^ (rB & 7)) << 3) + tig * 2);
            *oA = __floats2half2_rn(o[n][0], o[n][1]);
            *oB = __floats2half2_rn(o[n][2], o[n][3]);
        }
    }
}

// ===================== LayerNorm ===========================================
__global__ __launch_bounds__(256)
void ln_h(const __half* __restrict__ X,
          const float* __restrict__ gam, const float* __restrict__ bet,
          float* __restrict__ out32, __half* __restrict__ out16blk)
{
    const int t    = blockIdx.x;
    const int tid  = threadIdx.x;
    const int lane = tid & 31;
    const int wid  = tid >> 5;

    const size_t base = (size_t)t * DM + tid * 4;
    float2 a0 = __half22float2(*(const __half2*)(X + base));
    float2 a1 = __half22float2(*(const __half2*)(X + base + 2));
    float x0 = a0.x, x1 = a0.y, x2 = a1.x, x3 = a1.y;

    float s = x0 + x1 + x2 + x3;
    float q = x0 * x0 + x1 * x1 + x2 * x2 + x3 * x3;
#pragma unroll
    for (int o = 16; o > 0; o >>= 1) {
        s += __shfl_xor_sync(0xffffffffu, s, o);
        q += __shfl_xor_sync(0xffffffffu, q, o);
    }
    __shared__ float rs[8], rq[8];
    if (lane == 0) { rs[wid] = s; rq[wid] = q; }
    __syncthreads();
    if (wid == 0) {
        s = (lane < 8) ? rs[lane] : 0.f;
        q = (lane < 8) ? rq[lane] : 0.f;
#pragma unroll
        for (int o = 4; o > 0; o >>= 1) {
            s += __shfl_xor_sync(0xffffffffu, s, o);
            q += __shfl_xor_sync(0xffffffffu, q, o);
        }
        if (lane == 0) { rs[0] = s; rq[0] = q; }
    }
    __syncthreads();
    const float mu   = rs[0] * (1.f / DM);
    const float var  = rq[0] * (1.f / DM) - mu * mu;
    const float rstd = rsqrtf(var + LN_EPS);

    float4 gv = *(const float4*)(gam + tid * 4);
    float4 bv = *(const float4*)(bet + tid * 4);
    float r0 = (x0 - mu) * rstd * gv.x + bv.x;
    float r1 = (x1 - mu) * rstd * gv.y + bv.y;
    float r2 = (x2 - mu) * rstd * gv.z + bv.z;
    float r3 = (x3 - mu) * rstd * gv.w + bv.w;
    if (out32) {
        float4 r;
        r.x = r0; r.y = r1; r.z = r2; r.w = r3;
        *(float4*)(out32 + base) = r;
    }
    if (out16blk) {
        const size_t off = blk_off(t, tid * 4, DM);
        __half2* d = (__half2*)(out16blk + off);
        d[0] = __floats2half2_rn(r0, r1);
        d[1] = __floats2half2_rn(r2, r3);
    }
}

// ============ fused fp32 row-major -> blocked swizzled fp16 ================
constexpr int G_SRC = T * DM / 8;
constexpr int G_WIN = 3 * DM * DM / 8;
constexpr int G_WO  = DM * DM / 8;
constexpr int G_W1  = FF * DM / 8;
constexpr int G_W2  = DM * FF / 8;
constexpr int G_ALL = G_SRC + G_WIN + G_WO + G_W1 + G_W2;

__device__ __forceinline__ void cvt_one(const float* __restrict__ Wf,
                                        __half* __restrict__ Wb,
                                        int gi, int K)
{
    const int GPK = K >> 3;
    int n  = gi / GPK;
    int k0 = (gi - n * GPK) << 3;

    const float* src = Wf + (size_t)n * K + k0;
    float4 v0 = *(const float4*)(src);
    float4 v1 = *(const float4*)(src + 4);

    int nt = n >> 7, r = n & 127;
    int kt = k0 >> 6;
    int g  = (k0 & 63) >> 3;
    int gs = g ^ (r & 7);
    size_t off = ((((size_t)nt * (K >> 6)) + kt) << 13) + (size_t)r * 64 + gs * 8;
    __half2* dst = (__half2*)(Wb + off);
    dst[0] = __floats2half2_rn(v0.x, v0.y);
    dst[1] = __floats2half2_rn(v0.z, v0.w);
    dst[2] = __floats2half2_rn(v1.x, v1.y);
    dst[3] = __floats2half2_rn(v1.z, v1.w);
}

__global__ __launch_bounds__(256)
void cvt_all(const float* __restrict__ s0, const float* __restrict__ s1,
             const float* __restrict__ s2, const float* __restrict__ s3,
             const float* __restrict__ s4)
{
    int i = blockIdx.x * 256 + threadIdx.x;
    if (i < G_SRC)                  { cvt_one(s0, g_src_b,  i, DM); return; }
    if ((i -= G_SRC) < G_WIN)       { cvt_one(s1, g_win_b,  i, DM); return; }
    if ((i -= G_WIN) < G_WO)        { cvt_one(s2, g_wout_b, i, DM); return; }
    if ((i -= G_WO)  < G_W1)        { cvt_one(s3, g_w1_b,   i, DM); return; }
    if ((i -= G_W1)  < G_W2)        { cvt_one(s4, g_w2_b,   i, FF); return; }
}

// ---------------------------------------------------------------------------
extern "C" void kernel_launch(void* const* d_in, const int* in_sizes, int n_in,
                              void* d_out, int out_size)
{
    const float* src   = (const float*)d_in[0];
    const float* in_w  = (const float*)d_in[1];
    const float* in_b  = (const float*)d_in[2];
    const float* ow    = (const float*)d_in[3];
    const float* ob    = (const float*)d_in[4];
    const float* w1    = (const float*)d_in[5];
    const float* b1    = (const float*)d_in[6];
    const float* w2    = (const float*)d_in[7];
    const float* b2    = (const float*)d_in[8];
    const float* ln1g  = (const float*)d_in[9];
    const float* ln1b  = (const float*)d_in[10];
    const float* ln2g  = (const float*)d_in[11];
    const float* ln2b  = (const float*)d_in[12];
    float* out = (float*)d_out;

    __half *src_b, *win_b, *wout_b, *w1_b, *w2_b, *ctx_b, *h16_b, *ff_b, *x16;
    cudaGetSymbolAddress((void**)&src_b,  g_src_b);
    cudaGetSymbolAddress((void**)&win_b,  g_win_b);
    cudaGetSymbolAddress((void**)&wout_b, g_wout_b);
    cudaGetSymbolAddress((void**)&w1_b,   g_w1_b);
    cudaGetSymbolAddress((void**)&w2_b,   g_w2_b);
    __half* qkv_b;
    cudaGetSymbolAddress((void**)&qkv_b,  g_qkv_b);
    cudaGetSymbolAddress((void**)&ctx_b,  g_ctx_b);
    cudaGetSymbolAddress((void**)&h16_b,  g_h16_b);
    cudaGetSymbolAddress((void**)&ff_b,   g_ff_b);
    cudaGetSymbolAddress((void**)&x16,    g_x16);

    cudaFuncSetAttribute(gemm_h<1, 0, 0, DM>, cudaFuncAttributeMaxDynamicSharedMemorySize, GEMM_SMEM);
    cudaFuncSetAttribute(gemm_h<0, 0, 1, DM>, cudaFuncAttributeMaxDynamicSharedMemorySize, GEMM_SMEM);
    cudaFuncSetAttribute(gemm_h<1, 1, 0, DM>, cudaFuncAttributeMaxDynamicSharedMemorySize, GEMM_SMEM);
    cudaFuncSetAttribute(gemm_h<0, 0, 1, FF>, cudaFuncAttributeMaxDynamicSharedMemorySize, GEMM_SMEM);
    cudaFuncSetAttribute(attn_h, cudaFuncAttributeMaxDynamicSharedMemorySize, ATTN_SMEM);

    int nsm = 148;
    cudaDeviceGetAttribute(&nsm, cudaDevAttrMultiProcessorCount, 0);
    const int PGRID = 2 * nsm;

    // 0. fused converts
    cvt_all<<<(G_ALL + 255) / 256, 256>>>(src, in_w, ow, w1, w2);
    // 1. qkv (blocked)
    gemm_h<1, 0, 0, DM><<<PGRID, 128, GEMM_SMEM>>>(
        src_b, win_b, in_b, nullptr, qkv_b, T, 3 * DM);
    // 2. attention
    attn_h<<<dim3(NH, NWIN, BB), 256, ATTN_SMEM>>>();
    // 3. out-proj + residual (row out)
    gemm_h<0, 0, 1, DM><<<PGRID, 128, GEMM_SMEM>>>(
        ctx_b, wout_b, ob, src_b, x16, T, DM);
    // 4. LN1 -> blocked
    ln_h<<<T, 256>>>(x16, ln1g, ln1b, nullptr, h16_b);
    // 5. FFN1 (relu, blocked)
    gemm_h<1, 1, 0, DM><<<PGRID, 128, GEMM_SMEM>>>(
        h16_b, w1_b, b1, nullptr, ff_b, T, FF);
    // 6. FFN2 + residual (row out)
    gemm_h<0, 0, 1, FF><<<PGRID, 128, GEMM_SMEM>>>(
        ff_b, w2_b, b2, h16_b, x16, T, DM);
    // 7. LN2 -> out
    ln_h<<<T, 256>>>(x16, ln2g, ln2b, out, nullptr);
}

// round 17
// speedup vs baseline: 1.0604x; 1.0604x over previous
#include <cuda_runtime.h>
#include <cuda_fp16.h>
#include <cstdint>

// ---------------------------------------------------------------------------
// MultiAttnLayer, sm_103 baseline-ISA path. Round 17: R15 GEMM (natural grid,
// preserves L2 A-panel sharing that R16's persistent mapping destroyed) +
// R16's fused single-launch convert. Bulk-DMA stage ring, blocked swizzled
// tiles end-to-end, cross-iteration fragment prefetch, fp16 dataflow.
// ---------------------------------------------------------------------------

constexpr int BB   = 4;
constexpr int SEQ  = 8192;
constexpr int DM   = 1024;
constexpr int NH   = 16;
constexpr int HD   = 64;
constexpr int WIN  = 128;
constexpr int NWIN = SEQ / WIN;
constexpr int FF   = 4096;
constexpr int T    = BB * SEQ;
constexpr float LN_EPS = 1e-5f;

// Scratch (device globals). *_b = blocked swizzled 128x64 tiles.
__device__ __half g_src_b[(size_t)T * DM];
__device__ __half g_win_b[3 * DM * DM];
__device__ __half g_wout_b[DM * DM];
__device__ __half g_w1_b[FF * DM];
__device__ __half g_w2_b[DM * FF];
__device__ __half g_qkv_b[(size_t)T * 3 * DM];
__device__ __half g_ctx_b[(size_t)T * DM];
__device__ __half g_h16_b[(size_t)T * DM];
__device__ __half g_ff_b[(size_t)T * FF];
__device__ __half g_x16[(size_t)T * DM];

// ========================= helpers =========================================
__device__ __forceinline__ uint32_t smem_u32(const void* p) {
    uint32_t a;
    asm("{ .reg .u64 t; cvta.to.shared.u64 t, %1; cvt.u32.u64 %0, t; }" : "=r"(a) : "l"(p));
    return a;
}
__device__ __forceinline__ void bulk_g2s(uint32_t dst, const void* src,
                                         uint32_t bytes, uint32_t mbar) {
    asm volatile(
        "cp.async.bulk.shared::cluster.global.mbarrier::complete_tx::bytes "
        "[%0], [%1], %2, [%3];"
        :: "r"(dst), "l"(src), "r"(bytes), "r"(mbar) : "memory");
}
#define MBARRIER_INIT(addr, cnt) \
    asm volatile("mbarrier.init.shared.b64 [%0], %1;" :: "r"((uint32_t)(addr)), "r"((uint32_t)(cnt)) : "memory")
#define MBARRIER_EXPECT_TX(addr, tx) \
    asm volatile("mbarrier.arrive.expect_tx.shared.b64 _, [%0], %1;" \
        :: "r"((uint32_t)(addr)), "r"((uint32_t)(tx)) : "memory")
#define MBARRIER_WAIT_PARITY(addr, ph) do {                                      \
    uint32_t _m = (uint32_t)(addr), _p = (uint32_t)(ph), _d;                     \
    asm volatile("{ .reg .pred p; mbarrier.try_wait.parity.acquire.cta.shared::cta.b64 p, [%1], %2; selp.b32 %0, 1, 0, p; }" \
        : "=r"(_d) : "r"(_m), "r"(_p) : "memory");                               \
    if (!_d) {                                                                   \
        asm volatile("{ .reg .pred P1; WL_%=: mbarrier.try_wait.parity.acquire.cta.shared::cta.b64 P1, [%0], %1, 0x989680; @P1 bra.uni WD_%=; bra.uni WL_%=; WD_%=: }" \
            :: "r"(_m), "r"(_p) : "memory");                                     \
    }                                                                            \
} while (0)
#define LDSM_X4(r0, r1, r2, r3, addr)                                          \
    asm volatile("ldmatrix.sync.aligned.m8n8.x4.shared.b16 {%0,%1,%2,%3}, [%4];" \
        : "=r"(r0), "=r"(r1), "=r"(r2), "=r"(r3) : "r"(addr))
#define LDSM_X4_T(r0, r1, r2, r3, addr)                                        \
    asm volatile("ldmatrix.sync.aligned.m8n8.x4.trans.shared.b16 {%0,%1,%2,%3}, [%4];" \
        : "=r"(r0), "=r"(r1), "=r"(r2), "=r"(r3) : "r"(addr))

__device__ __forceinline__ void mma_f16(float c[4], const uint32_t a[4],
                                        uint32_t b0, uint32_t b1) {
    asm volatile(
        "mma.sync.aligned.m16n8k16.row.col.f32.f16.f16.f32 "
        "{%0,%1,%2,%3}, {%4,%5,%6,%7}, {%8,%9}, {%0,%1,%2,%3};\n"
        : "+f"(c[0]), "+f"(c[1]), "+f"(c[2]), "+f"(c[3])
        : "r"(a[0]), "r"(a[1]), "r"(a[2]), "r"(a[3]), "r"(b0), "r"(b1));
}

__device__ __forceinline__ size_t blk_off(int row, int col, int C) {
    int tile = (row >> 7) * (C >> 6) + (col >> 6);
    int r = row & 127;
    int g = (col & 63) >> 3;
    return ((size_t)tile << 13) + (size_t)r * 64 + (size_t)((g ^ (r & 7)) << 3) + (col & 7);
}

// ========================= fp16 GEMM =======================================
constexpr int BM = 128, BN = 128, BK = 64, STAGES = 3;
constexpr int TILE_B  = 16384;
constexpr int ST      = 2 * TILE_B;
constexpr int MBAR_OFF = STAGES * ST;
constexpr int GEMM_SMEM = MBAR_OFF + 32;

template <int OUT_BLK, int RELU, int RES, int KV>
__global__ __launch_bounds__(128, 2)
void gemm_h(const __half* __restrict__ Ablk, const __half* __restrict__ Wblk,
            const float* __restrict__ bias, const __half* __restrict__ Res,
            __half* __restrict__ Cout, int M, int N)
{
    extern __shared__ char smraw[];
    const uint32_t sb = smem_u32(smraw);
    const uint32_t mb = sb + MBAR_OFF;

    const int tid  = threadIdx.x;
    const int wid  = tid >> 5;
    const int lane = tid & 31;
    const int wm   = wid >> 1;
    const int wn   = wid & 1;
    const int bm   = blockIdx.y * BM;
    const int bn   = blockIdx.x * BN;
    constexpr int K  = KV;
    constexpr int KT = K / 64;
    const __half* atile0 = Ablk + ((size_t)(bm >> 7) * KT << 13);
    const __half* wtile0 = Wblk + ((size_t)(bn >> 7) * KT << 13);

    float acc[4][8][4];
#pragma unroll
    for (int i = 0; i < 4; i++)
#pragma unroll
        for (int j = 0; j < 8; j++)
#pragma unroll
            for (int l = 0; l < 4; l++) acc[i][j][l] = 0.f;

    if (tid == 0) {
#pragma unroll
        for (int s = 0; s < STAGES; s++) MBARRIER_INIT(mb + s * 8, 1);
    }
    __syncthreads();

    constexpr int NK = K / BK;
    if (tid == 0) {
#pragma unroll
        for (int s = 0; s < STAGES - 1; s++) {
            MBARRIER_EXPECT_TX(mb + s * 8, (uint32_t)ST);
            bulk_g2s(sb + s * ST,          atile0 + ((size_t)s << 13), TILE_B, mb + s * 8);
            bulk_g2s(sb + s * ST + TILE_B, wtile0 + ((size_t)s << 13), TILE_B, mb + s * 8);
        }
    }

    const int r7A = lane & 7;
    const int hbA = lane >> 4;
    const uint32_t a_rowbyte = (uint32_t)((wm * 64 + (lane & 15)) * 128);
    const int r7B = lane & 7;
    const int hbB = (lane >> 3) & 1;
    const uint32_t b_rowbyte = (uint32_t)((wn * 64 + (lane & 7) + ((lane >> 4) & 1) * 8) * 128);

    uint32_t a_f[2][4][4];
    uint32_t b_f[2][8][2];

    // Initial prime: wait stage 0, load (k=0, ks=0) fragments into buffer 0.
    MBARRIER_WAIT_PARITY(mb, 0);
    {
        const uint32_t a_row = sb + a_rowbyte;
        const uint32_t b_row = sb + TILE_B + b_rowbyte;
        const uint32_t ax = (uint32_t)((hbA ^ r7A) << 4);
#pragma unroll
        for (int im = 0; im < 4; im++)
            LDSM_X4(a_f[0][im][0], a_f[0][im][1], a_f[0][im][2], a_f[0][im][3],
                    a_row + im * 2048 + ax);
        const uint32_t bx = (uint32_t)((hbB ^ r7B) << 4);
#pragma unroll
        for (int p = 0; p < 4; p++) {
            uint32_t r0, r1, r2, r3;
            LDSM_X4(r0, r1, r2, r3, b_row + p * 2048 + bx);
            b_f[0][2 * p][0] = r0; b_f[0][2 * p][1] = r1;
            b_f[0][2 * p + 1][0] = r2; b_f[0][2 * p + 1][1] = r3;
        }
    }

    for (int k = 0; k < NK; k++) {
        __syncthreads();   // all warps finished reading slot (k+2)%S (iter k-1)
        if (k + STAGES - 1 < NK && tid == 0) {
            const int kn = k + STAGES - 1;
            const int sN = kn % STAGES;
            MBARRIER_EXPECT_TX(mb + sN * 8, (uint32_t)ST);
            bulk_g2s(sb + sN * ST,          atile0 + ((size_t)kn << 13), TILE_B, mb + sN * 8);
            bulk_g2s(sb + sN * ST + TILE_B, wtile0 + ((size_t)kn << 13), TILE_B, mb + sN * 8);
        }

        const uint32_t aSt = sb + (k % STAGES) * ST;
        const uint32_t a_row = aSt + a_rowbyte;
        const uint32_t b_row = aSt + TILE_B + b_rowbyte;

#pragma unroll
        for (int ks = 0; ks < 4; ks++) {
            const int cb = ks & 1;
            const int nb = cb ^ 1;
            if (ks < 3) {
                const uint32_t ax = (uint32_t)(((2 * (ks + 1) + hbA) ^ r7A) << 4);
#pragma unroll
                for (int im = 0; im < 4; im++)
                    LDSM_X4(a_f[nb][im][0], a_f[nb][im][1], a_f[nb][im][2], a_f[nb][im][3],
                            a_row + im * 2048 + ax);
                const uint32_t bx = (uint32_t)(((2 * (ks + 1) + hbB) ^ r7B) << 4);
#pragma unroll
                for (int p = 0; p < 4; p++) {
                    uint32_t r0, r1, r2, r3;
                    LDSM_X4(r0, r1, r2, r3, b_row + p * 2048 + bx);
                    b_f[nb][2 * p][0] = r0; b_f[nb][2 * p][1] = r1;
                    b_f[nb][2 * p + 1][0] = r2; b_f[nb][2 * p + 1][1] = r3;
                }
            } else if (k + 1 < NK) {
                MBARRIER_WAIT_PARITY(mb + ((k + 1) % STAGES) * 8, ((k + 1) / STAGES) & 1);
                const uint32_t aS2 = sb + ((k + 1) % STAGES) * ST;
                const uint32_t aR2 = aS2 + a_rowbyte;
                const uint32_t bR2 = aS2 + TILE_B + b_rowbyte;
                const uint32_t ax = (uint32_t)((hbA ^ r7A) << 4);
#pragma unroll
                for (int im = 0; im < 4; im++)
                    LDSM_X4(a_f[nb][im][0], a_f[nb][im][1], a_f[nb][im][2], a_f[nb][im][3],
                            aR2 + im * 2048 + ax);
                const uint32_t bx = (uint32_t)((hbB ^ r7B) << 4);
#pragma unroll
                for (int p = 0; p < 4; p++) {
                    uint32_t r0, r1, r2, r3;
                    LDSM_X4(r0, r1, r2, r3, bR2 + p * 2048 + bx);
                    b_f[nb][2 * p][0] = r0; b_f[nb][2 * p][1] = r1;
                    b_f[nb][2 * p + 1][0] = r2; b_f[nb][2 * p + 1][1] = r3;
                }
            }
#pragma unroll
            for (int im = 0; im < 4; im++)
#pragma unroll
                for (int n = 0; n < 8; n++)
                    mma_f16(acc[im][n], a_f[cb][im], b_f[cb][n][0], b_f[cb][n][1]);
        }
    }

    // Epilogue
#pragma unroll
    for (int im = 0; im < 4; im++) {
        const int row = bm + wm * 64 + im * 16 + (lane >> 2);
#pragma unroll
        for (int n = 0; n < 8; n++) {
            const int col = bn + wn * 64 + n * 8 + (lane & 3) * 2;
            const float2 bv = *(const float2*)(bias + col);
            float v00 = acc[im][n][0] + bv.x, v01 = acc[im][n][1] + bv.y;
            float v10 = acc[im][n][2] + bv.x, v11 = acc[im][n][3] + bv.y;
            if (RES) {
                const float2 r0 = __half22float2(
                    *(const __half2*)(Res + blk_off(row, col, N)));
                const float2 r1 = __half22float2(
                    *(const __half2*)(Res + blk_off(row + 8, col, N)));
                v00 += r0.x; v01 += r0.y;
                v10 += r1.x; v11 += r1.y;
            }
            if (RELU) {
                v00 = fmaxf(v00, 0.f); v01 = fmaxf(v01, 0.f);
                v10 = fmaxf(v10, 0.f); v11 = fmaxf(v11, 0.f);
            }
            if (OUT_BLK) {
                *(__half2*)(Cout + blk_off(row, col, N))     = __floats2half2_rn(v00, v01);
                *(__half2*)(Cout + blk_off(row + 8, col, N)) = __floats2half2_rn(v10, v11);
            } else {
                *(__half2*)(Cout + (size_t)row * N + col)       = __floats2half2_rn(v00, v01);
                *(__half2*)(Cout + (size_t)(row + 8) * N + col) = __floats2half2_rn(v10, v11);
            }
        }
    }
}

// ===================== window-local attention ==============================
constexpr int ATT_MB   = 0;
constexpr int OFF_Q    = 1024;
constexpr int OFF_K    = OFF_Q + TILE_B;
constexpr int OFF_V    = OFF_K + TILE_B;
constexpr int OFF_P    = OFF_V + TILE_B;
constexpr int P_ROWB   = 272;
constexpr int ATTN_SMEM = OFF_P + 128 * P_ROWB;

__global__ __launch_bounds__(256, 2)
void attn_h()
{
    extern __shared__ char smraw[];
    const uint32_t sb = smem_u32(smraw);
    const uint32_t mb = sb + ATT_MB;
    const uint32_t qh = sb + OFF_Q;
    const uint32_t kh = sb + OFF_K;
    const uint32_t vh = sb + OFF_V;

    const int h  = blockIdx.x;
    const int w  = blockIdx.y;
    const int b  = blockIdx.z;
    const int t0 = b * SEQ + w * WIN;
    const int rt = t0 >> 7;

    const int tid  = threadIdx.x;
    const int wid  = tid >> 5;
    const int lane = tid & 31;
    const int gid  = lane >> 2;
    const int tig  = lane & 3;

    if (tid == 0) MBARRIER_INIT(mb, 1);
    __syncthreads();
    if (tid == 0) {
        MBARRIER_EXPECT_TX(mb, 3u * TILE_B);
        const size_t trow = (size_t)rt * 48;
        bulk_g2s(qh, g_qkv_b + ((trow + h)      << 13), TILE_B, mb);
        bulk_g2s(kh, g_qkv_b + ((trow + 16 + h) << 13), TILE_B, mb);
        bulk_g2s(vh, g_qkv_b + ((trow + 32 + h) << 13), TILE_B, mb);
    }
    MBARRIER_WAIT_PARITY(mb, 0);

    const int m0 = wid * 16;

    float sc[16][4];
#pragma unroll
    for (int n = 0; n < 16; n++)
#pragma unroll
        for (int l = 0; l < 4; l++) sc[n][l] = 0.f;

    const int aRow = m0 + (lane & 15);
    const int aHb  = lane >> 4;
    const uint32_t a_row = qh + (uint32_t)aRow * 128;
    const int aR7 = aRow & 7;
    const int bRowBase = (lane & 7) + ((lane >> 4) & 1) * 8;
    const int bHb = (lane >> 3) & 1;

#pragma unroll
    for (int ks = 0; ks < 4; ks++) {
        uint32_t a[4];
        LDSM_X4(a[0], a[1], a[2], a[3], a_row + (uint32_t)(((2 * ks + aHb) ^ aR7) << 4));
#pragma unroll
        for (int p = 0; p < 8; p++) {
            const int brow = bRowBase + p * 16;
            const uint32_t baddr = kh + (uint32_t)brow * 128 +
                                   (uint32_t)(((2 * ks + bHb) ^ (brow & 7)) << 4);
            uint32_t r0, r1, r2, r3;
            LDSM_X4(r0, r1, r2, r3, baddr);
            mma_f16(sc[2 * p], a, r0, r1);
            mma_f16(sc[2 * p + 1], a, r2, r3);
        }
    }

    const float scale = 0.125f;
    float mA = -1e30f, mB = -1e30f;
#pragma unroll
    for (int n = 0; n < 16; n++) {
#pragma unroll
        for (int l = 0; l < 4; l++) sc[n][l] *= scale;
        mA = fmaxf(mA, fmaxf(sc[n][0], sc[n][1]));
        mB = fmaxf(mB, fmaxf(sc[n][2], sc[n][3]));
    }
    mA = fmaxf(mA, __shfl_xor_sync(0xffffffffu, mA, 1));
    mA = fmaxf(mA, __shfl_xor_sync(0xffffffffu, mA, 2));
    mB = fmaxf(mB, __shfl_xor_sync(0xffffffffu, mB, 1));
    mB = fmaxf(mB, __shfl_xor_sync(0xffffffffu, mB, 2));

    float sA = 0.f, sB = 0.f;
#pragma unroll
    for (int n = 0; n < 16; n++) {
        sc[n][0] = __expf(sc[n][0] - mA);
        sc[n][1] = __expf(sc[n][1] - mA);
        sc[n][2] = __expf(sc[n][2] - mB);
        sc[n][3] = __expf(sc[n][3] - mB);
        sA += sc[n][0] + sc[n][1];
        sB += sc[n][2] + sc[n][3];
    }
    sA += __shfl_xor_sync(0xffffffffu, sA, 1);
    sA += __shfl_xor_sync(0xffffffffu, sA, 2);
    sB += __shfl_xor_sync(0xffffffffu, sB, 1);
    sB += __shfl_xor_sync(0xffffffffu, sB, 2);
    const float invA = 1.f / sA, invB = 1.f / sB;

    {
        const int rA = m0 + gid;
        __half2* pA = (__half2*)(smraw + OFF_P + rA * P_ROWB);
        __half2* pB = (__half2*)(smraw + OFF_P + (rA + 8) * P_ROWB);
#pragma unroll
        for (int n = 0; n < 16; n++) {
            const int c2 = (n * 8 + tig * 2) >> 1;
            pA[c2] = __floats2half2_rn(sc[n][0] * invA, sc[n][1] * invA);
            pB[c2] = __floats2half2_rn(sc[n][2] * invB, sc[n][3] * invB);
        }
    }
    __syncthreads();

    float o[8][4];
#pragma unroll
    for (int n = 0; n < 8; n++)
#pragma unroll
        for (int l = 0; l < 4; l++) o[n][l] = 0.f;

    const uint32_t p_base = sb + OFF_P + (m0 + (lane & 15)) * P_ROWB + (lane >> 4) * 16;
    const int vRowBase = (lane & 7) + ((lane >> 3) & 1) * 8;
    const int vGb = lane >> 4;

#pragma unroll
    for (int ks = 0; ks < 8; ks++) {
        uint32_t a[4];
        LDSM_X4(a[0], a[1], a[2], a[3], p_base + ks * 32);
        const int vrow = vRowBase + ks * 16;
        const uint32_t vr = vh + (uint32_t)vrow * 128;
        const int v7 = vrow & 7;
#pragma unroll
        for (int p = 0; p < 4; p++) {
            uint32_t r0, r1, r2, r3;
            LDSM_X4_T(r0, r1, r2, r3, vr + (uint32_t)(((2 * p + vGb) ^ v7) << 4));
            mma_f16(o[2 * p], a, r0, r1);
            mma_f16(o[2 * p + 1], a, r2, r3);
        }
    }

    {
        const size_t tbase = (((size_t)rt * (DM >> 6)) + h) << 13;
        const int rA = m0 + gid;
        const int rB = rA + 8;
#pragma unroll
        for (int n = 0; n < 8; n++) {
            __half2* oA = (__half2*)(g_ctx_b + tbase + (size_t)rA * 64 +
                                     ((n ^ (rA & 7)) << 3) + tig * 2);
            __half2* oB = (__half2*)(g_ctx_b + tbase + (size_t)rB * 64 +
                                     ((n ^ (rB & 7)) << 3) + tig * 2);
            *oA = __floats2half2_rn(o[n][0], o[n][1]);
            *oB = __floats2half2_rn(o[n][2], o[n][3]);
        }
    }
}

// ===================== LayerNorm ===========================================
__global__ __launch_bounds__(256)
void ln_h(const __half* __restrict__ X,
          const float* __restrict__ gam, const float* __restrict__ bet,
          float* __restrict__ out32, __half* __restrict__ out16blk)
{
    const int t    = blockIdx.x;
    const int tid  = threadIdx.x;
    const int lane = tid & 31;
    const int wid  = tid >> 5;

    const size_t base = (size_t)t * DM + tid * 4;
    float2 a0 = __half22float2(*(const __half2*)(X + base));
    float2 a1 = __half22float2(*(const __half2*)(X + base + 2));
    float x0 = a0.x, x1 = a0.y, x2 = a1.x, x3 = a1.y;

    float s = x0 + x1 + x2 + x3;
    float q = x0 * x0 + x1 * x1 + x2 * x2 + x3 * x3;
#pragma unroll
    for (int o = 16; o > 0; o >>= 1) {
        s += __shfl_xor_sync(0xffffffffu, s, o);
        q += __shfl_xor_sync(0xffffffffu, q, o);
    }
    __shared__ float rs[8], rq[8];
    if (lane == 0) { rs[wid] = s; rq[wid] = q; }
    __syncthreads();
    if (wid == 0) {
        s = (lane < 8) ? rs[lane] : 0.f;
        q = (lane < 8) ? rq[lane] : 0.f;
#pragma unroll
        for (int o = 4; o > 0; o >>= 1) {
            s += __shfl_xor_sync(0xffffffffu, s, o);
            q += __shfl_xor_sync(0xffffffffu, q, o);
        }
        if (lane == 0) { rs[0] = s; rq[0] = q; }
    }
    __syncthreads();
    const float mu   = rs[0] * (1.f / DM);
    const float var  = rq[0] * (1.f / DM) - mu * mu;
    const float rstd = rsqrtf(var + LN_EPS);

    float4 gv = *(const float4*)(gam + tid * 4);
    float4 bv = *(const float4*)(bet + tid * 4);
    float r0 = (x0 - mu) * rstd * gv.x + bv.x;
    float r1 = (x1 - mu) * rstd * gv.y + bv.y;
    float r2 = (x2 - mu) * rstd * gv.z + bv.z;
    float r3 = (x3 - mu) * rstd * gv.w + bv.w;
    if (out32) {
        float4 r;
        r.x = r0; r.y = r1; r.z = r2; r.w = r3;
        *(float4*)(out32 + base) = r;
    }
    if (out16blk) {
        const size_t off = blk_off(t, tid * 4, DM);
        __half2* d = (__half2*)(out16blk + off);
        d[0] = __floats2half2_rn(r0, r1);
        d[1] = __floats2half2_rn(r2, r3);
    }
}

// ============ fused fp32 row-major -> blocked swizzled fp16 ================
constexpr int G_SRC = T * DM / 8;
constexpr int G_WIN = 3 * DM * DM / 8;
constexpr int G_WO  = DM * DM / 8;
constexpr int G_W1  = FF * DM / 8;
constexpr int G_W2  = DM * FF / 8;
constexpr int G_ALL = G_SRC + G_WIN + G_WO + G_W1 + G_W2;

__device__ __forceinline__ void cvt_one(const float* __restrict__ Wf,
                                        __half* __restrict__ Wb,
                                        int gi, int K)
{
    const int GPK = K >> 3;
    int n  = gi / GPK;
    int k0 = (gi - n * GPK) << 3;

    const float* src = Wf + (size_t)n * K + k0;
    float4 v0 = *(const float4*)(src);
    float4 v1 = *(const float4*)(src + 4);

    int nt = n >> 7, r = n & 127;
    int kt = k0 >> 6;
    int g  = (k0 & 63) >> 3;
    int gs = g ^ (r & 7);
    size_t off = ((((size_t)nt * (K >> 6)) + kt) << 13) + (size_t)r * 64 + gs * 8;
    __half2* dst = (__half2*)(Wb + off);
    dst[0] = __floats2half2_rn(v0.x, v0.y);
    dst[1] = __floats2half2_rn(v0.z, v0.w);
    dst[2] = __floats2half2_rn(v1.x, v1.y);
    dst[3] = __floats2half2_rn(v1.z, v1.w);
}

__global__ __launch_bounds__(256)
void cvt_all(const float* __restrict__ s0, const float* __restrict__ s1,
             const float* __restrict__ s2, const float* __restrict__ s3,
             const float* __restrict__ s4)
{
    int i = blockIdx.x * 256 + threadIdx.x;
    if (i < G_SRC)                  { cvt_one(s0, g_src_b,  i, DM); return; }
    if ((i -= G_SRC) < G_WIN)       { cvt_one(s1, g_win_b,  i, DM); return; }
    if ((i -= G_WIN) < G_WO)        { cvt_one(s2, g_wout_b, i, DM); return; }
    if ((i -= G_WO)  < G_W1)        { cvt_one(s3, g_w1_b,   i, DM); return; }
    if ((i -= G_W1)  < G_W2)        { cvt_one(s4, g_w2_b,   i, FF); return; }
}

// ---------------------------------------------------------------------------
extern "C" void kernel_launch(void* const* d_in, const int* in_sizes, int n_in,
                              void* d_out, int out_size)
{
    const float* src   = (const float*)d_in[0];
    const float* in_w  = (const float*)d_in[1];
    const float* in_b  = (const float*)d_in[2];
    const float* ow    = (const float*)d_in[3];
    const float* ob    = (const float*)d_in[4];
    const float* w1    = (const float*)d_in[5];
    const float* b1    = (const float*)d_in[6];
    const float* w2    = (const float*)d_in[7];
    const float* b2    = (const float*)d_in[8];
    const float* ln1g  = (const float*)d_in[9];
    const float* ln1b  = (const float*)d_in[10];
    const float* ln2g  = (const float*)d_in[11];
    const float* ln2b  = (const float*)d_in[12];
    float* out = (float*)d_out;

    __half *src_b, *win_b, *wout_b, *w1_b, *w2_b, *qkv_b, *ctx_b, *h16_b, *ff_b, *x16;
    cudaGetSymbolAddress((void**)&src_b,  g_src_b);
    cudaGetSymbolAddress((void**)&win_b,  g_win_b);
    cudaGetSymbolAddress((void**)&wout_b, g_wout_b);
    cudaGetSymbolAddress((void**)&w1_b,   g_w1_b);
    cudaGetSymbolAddress((void**)&w2_b,   g_w2_b);
    cudaGetSymbolAddress((void**)&qkv_b,  g_qkv_b);
    cudaGetSymbolAddress((void**)&ctx_b,  g_ctx_b);
    cudaGetSymbolAddress((void**)&h16_b,  g_h16_b);
    cudaGetSymbolAddress((void**)&ff_b,   g_ff_b);
    cudaGetSymbolAddress((void**)&x16,    g_x16);

    cudaFuncSetAttribute(gemm_h<1, 0, 0, DM>, cudaFuncAttributeMaxDynamicSharedMemorySize, GEMM_SMEM);
    cudaFuncSetAttribute(gemm_h<0, 0, 1, DM>, cudaFuncAttributeMaxDynamicSharedMemorySize, GEMM_SMEM);
    cudaFuncSetAttribute(gemm_h<1, 1, 0, DM>, cudaFuncAttributeMaxDynamicSharedMemorySize, GEMM_SMEM);
    cudaFuncSetAttribute(gemm_h<0, 0, 1, FF>, cudaFuncAttributeMaxDynamicSharedMemorySize, GEMM_SMEM);
    cudaFuncSetAttribute(attn_h, cudaFuncAttributeMaxDynamicSharedMemorySize, ATTN_SMEM);

    // 0. fused converts (single launch)
    cvt_all<<<(G_ALL + 255) / 256, 256>>>(src, in_w, ow, w1, w2);
    // 1. qkv (blocked)
    gemm_h<1, 0, 0, DM><<<dim3(3 * DM / BN, T / BM), 128, GEMM_SMEM>>>(
        src_b, win_b, in_b, nullptr, qkv_b, T, 3 * DM);
    // 2. attention
    attn_h<<<dim3(NH, NWIN, BB), 256, ATTN_SMEM>>>();
    // 3. out-proj + residual (row out)
    gemm_h<0, 0, 1, DM><<<dim3(DM / BN, T / BM), 128, GEMM_SMEM>>>(
        ctx_b, wout_b, ob, src_b, x16, T, DM);
    // 4. LN1 -> blocked
    ln_h<<<T, 256>>>(x16, ln1g, ln1b, nullptr, h16_b);
    // 5. FFN1 (relu, blocked)
    gemm_h<1, 1, 0, DM><<<dim3(FF / BN, T / BM), 128, GEMM_SMEM>>>(
        h16_b, w1_b, b1, nullptr, ff_b, T, FF);
    // 6. FFN2 + residual (row out)
    gemm_h<0, 0, 1, FF><<<dim3(DM / BN, T / BM), 128, GEMM_SMEM>>>(
        ff_b, w2_b, b2, h16_b, x16, T, DM);
    // 7. LN2 -> out
    ln_h<<<T, 256>>>(x16, ln2g, ln2b, out, nullptr);
}